// round 10
// baseline (speedup 1.0000x reference)
#include <cuda_runtime.h>
#include <math.h>

static constexpr int B_DIM = 8192;
static constexpr int N_PTS = 1024;
static constexpr int THREADS = 256;
static constexpr int GRID = 740;          // 148 SMs * 5 CTAs/SM = one full wave

// Allocation-free scratch (__device__ globals per harness rules).
__device__ double g_acc;
__device__ unsigned int g_ticket;
__device__ float g_D[B_DIM * 12];         // D padded to 12 floats/row (3x float4)

__device__ __forceinline__ void euler_to_matrix(float a, float b, float c, float* R) {
    const float sa = sinf(a), ca = cosf(a);
    const float sb = sinf(b), cb = cosf(b);
    const float sc = sinf(c), cc = cosf(c);
    // R = Rx(a) * Ry(b) * Rz(c)
    R[0] = cb * cc;
    R[1] = -cb * sc;
    R[2] = sb;
    R[3] = ca * sc + sa * sb * cc;
    R[4] = ca * cc - sa * sb * sc;
    R[5] = -sa * cb;
    R[6] = sa * sc - ca * sb * cc;
    R[7] = sa * cc + ca * sb * sc;
    R[8] = ca * cb;
}

// Kernel 1: per-row trig + matrix difference (8192 parallel threads) + state reset.
__global__ __launch_bounds__(256)
void precompute_kernel(const float* __restrict__ pred,
                       const float* __restrict__ mode,
                       const float* __restrict__ gt) {
    const int b = blockIdx.x * blockDim.x + threadIdx.x;
    if (b == 0) { g_acc = 0.0; g_ticket = 0u; }
    if (b >= B_DIM) return;

    const float m1 = pred[b * 4 + 0];
    const float m2 = pred[b * 4 + 1];
    const float m3 = pred[b * 4 + 2];
    const float m4 = pred[b * 4 + 3];
    const float sgn = (mode[b] > 0.5f) ? 1.0f : -1.0f;
    const float denom = m1 * m1 + m2 * m2 + m3 * m3;
    const float e2 = sgn * asinf(sqrtf(m3 * m3 / denom));
    const float se2 = sinf(e2);
    const float ce2 = cosf(e2);
    const float e3 = atan2f(m4, m3 / (se2 + 1e-9f));
    const float tmp = ce2 * cosf(e3);
    const float e1 = atan2f(m2 / tmp, m1 / tmp);
    // (ref's +2pi wrap of euler3 only shifts by a full period; sin/cos unchanged)

    float Rp[9], Rg[9];
    euler_to_matrix(e1, e2, e3, Rp);
    euler_to_matrix(gt[b * 3 + 0], gt[b * 3 + 1], gt[b * 3 + 2], Rg);

    float4* dst = (float4*)(g_D + b * 12);  // 48B row stride, 16B aligned
    dst[0] = make_float4(Rp[0] - Rg[0], Rp[1] - Rg[1], Rp[2] - Rg[2], Rp[3] - Rg[3]);
    dst[1] = make_float4(Rp[4] - Rg[4], Rp[5] - Rg[5], Rp[6] - Rg[6], Rp[7] - Rg[7]);
    dst[2] = make_float4(Rp[8] - Rg[8], 0.0f, 0.0f, 0.0f);
}

// Kernel 2: persistent, software-pipelined streaming. Prefetch next row's data
// (3 point float4s + 3 D float4s) before computing the current row.
__global__ __launch_bounds__(THREADS, 5)
void add_loss_kernel(const float* __restrict__ point, float* __restrict__ out) {
    __shared__ float warp_sums[THREADS / 32];

    const int t = threadIdx.x;
    float acc = 0.0f;

    int b = blockIdx.x;
    // Prologue: load first row.
    float4 av, bv, cv, D0, D1, D2;
    {
        const float4* __restrict__ r = (const float4*)(point + (size_t)b * (N_PTS * 3));
        av = r[3 * t + 0]; bv = r[3 * t + 1]; cv = r[3 * t + 2];
        const float4* __restrict__ d = (const float4*)(g_D + b * 12);
        D0 = d[0]; D1 = d[1]; D2 = d[2];
    }

    #pragma unroll 1
    while (b < B_DIM) {
        const int nb = b + GRID;
        float4 nav, nbv, ncv, nD0, nD1, nD2;
        if (nb < B_DIM) {   // prefetch (predicated LDG; in flight during compute)
            const float4* __restrict__ r = (const float4*)(point + (size_t)nb * (N_PTS * 3));
            nav = r[3 * t + 0]; nbv = r[3 * t + 1]; ncv = r[3 * t + 2];
            const float4* __restrict__ d = (const float4*)(g_D + nb * 12);
            nD0 = d[0]; nD1 = d[1]; nD2 = d[2];
        } else {
            nav = nbv = ncv = nD0 = nD1 = nD2 = make_float4(0.f, 0.f, 0.f, 0.f);
        }

        // Compute on current row (4 points per thread).
        const float d00 = D0.x, d01 = D0.y, d02 = D0.z;
        const float d10 = D0.w, d11 = D1.x, d12 = D1.y;
        const float d20 = D1.z, d21 = D1.w, d22 = D2.x;
        const float px[4] = {av.x, av.w, bv.z, cv.y};
        const float py[4] = {av.y, bv.x, bv.w, cv.z};
        const float pz[4] = {av.z, bv.y, cv.x, cv.w};
        #pragma unroll
        for (int i = 0; i < 4; i++) {
            const float q0 = fmaf(px[i], d00, fmaf(py[i], d10, pz[i] * d20));
            const float q1 = fmaf(px[i], d01, fmaf(py[i], d11, pz[i] * d21));
            const float q2 = fmaf(px[i], d02, fmaf(py[i], d12, pz[i] * d22));
            acc += sqrtf(fmaf(q0, q0, fmaf(q1, q1, q2 * q2)));
        }

        // Rotate buffers.
        av = nav; bv = nbv; cv = ncv; D0 = nD0; D1 = nD1; D2 = nD2;
        b = nb;
    }

    // One reduce + one atomic per CTA.
    #pragma unroll
    for (int off = 16; off > 0; off >>= 1)
        acc += __shfl_xor_sync(0xffffffffu, acc, off);
    if ((t & 31) == 0) warp_sums[t >> 5] = acc;
    __syncthreads();

    if (t == 0) {
        float s = 0.0f;
        #pragma unroll
        for (int w = 0; w < THREADS / 32; w++) s += warp_sums[w];
        atomicAdd(&g_acc, (double)s);
        __threadfence();
        const unsigned int ticket = atomicAdd(&g_ticket, 1u);
        if (ticket == (unsigned int)(gridDim.x - 1)) {
            __threadfence();
            const double total = atomicAdd(&g_acc, 0.0);
            out[0] = (float)(total * (1.0 / ((double)B_DIM * (double)N_PTS)));
        }
    }
}

extern "C" void kernel_launch(void* const* d_in, const int* in_sizes, int n_in,
                              void* d_out, int out_size) {
    const float* pred  = (const float*)d_in[0];   // (8192, 4)
    const float* mode  = (const float*)d_in[1];   // (8192,)
    const float* gt    = (const float*)d_in[2];   // (8192, 3)
    const float* point = (const float*)d_in[3];   // (8192, 1024, 3)
    float* out = (float*)d_out;

    precompute_kernel<<<B_DIM / 256, 256>>>(pred, mode, gt);
    add_loss_kernel<<<GRID, THREADS>>>(point, out);
}

// round 12
// speedup vs baseline: 1.3176x; 1.3176x over previous
#include <cuda_runtime.h>
#include <math.h>

static constexpr int B_DIM = 8192;
static constexpr int N_PTS = 1024;
static constexpr int THREADS = 256;
static constexpr int GRID = 888;          // 148 SMs * 6 CTAs/SM

// Allocation-free scratch (__device__ globals per harness rules).
__device__ double g_acc;
__device__ unsigned int g_ticket;
__device__ float g_D[B_DIM * 12];         // D padded to 12 floats/row (3x float4)

__device__ __forceinline__ float fast_sqrt(float x) {
    float r;
    asm("sqrt.approx.f32 %0, %1;" : "=f"(r) : "f"(x));
    return r;
}

__device__ __forceinline__ void euler_to_matrix(float a, float b, float c, float* R) {
    const float sa = sinf(a), ca = cosf(a);
    const float sb = sinf(b), cb = cosf(b);
    const float sc = sinf(c), cc = cosf(c);
    // R = Rx(a) * Ry(b) * Rz(c)
    R[0] = cb * cc;
    R[1] = -cb * sc;
    R[2] = sb;
    R[3] = ca * sc + sa * sb * cc;
    R[4] = ca * cc - sa * sb * sc;
    R[5] = -sa * cb;
    R[6] = sa * sc - ca * sb * cc;
    R[7] = sa * cc + ca * sb * sc;
    R[8] = ca * cb;
}

// Kernel 1: per-row trig + matrix difference (8192 parallel threads) + state reset.
__global__ __launch_bounds__(256)
void precompute_kernel(const float* __restrict__ pred,
                       const float* __restrict__ mode,
                       const float* __restrict__ gt) {
    const int b = blockIdx.x * blockDim.x + threadIdx.x;
    if (b == 0) { g_acc = 0.0; g_ticket = 0u; }
    if (b >= B_DIM) return;

    const float m1 = pred[b * 4 + 0];
    const float m2 = pred[b * 4 + 1];
    const float m3 = pred[b * 4 + 2];
    const float m4 = pred[b * 4 + 3];
    const float sgn = (mode[b] > 0.5f) ? 1.0f : -1.0f;
    const float denom = m1 * m1 + m2 * m2 + m3 * m3;
    const float e2 = sgn * asinf(sqrtf(m3 * m3 / denom));
    const float se2 = sinf(e2);
    const float ce2 = cosf(e2);
    const float e3 = atan2f(m4, m3 / (se2 + 1e-9f));
    const float tmp = ce2 * cosf(e3);
    const float e1 = atan2f(m2 / tmp, m1 / tmp);
    // (ref's +2pi wrap of euler3 only shifts by a full period; sin/cos unchanged)

    float Rp[9], Rg[9];
    euler_to_matrix(e1, e2, e3, Rp);
    euler_to_matrix(gt[b * 3 + 0], gt[b * 3 + 1], gt[b * 3 + 2], Rg);

    float4* dst = (float4*)(g_D + b * 12);  // 48B row stride, 16B aligned
    dst[0] = make_float4(Rp[0] - Rg[0], Rp[1] - Rg[1], Rp[2] - Rg[2], Rp[3] - Rg[3]);
    dst[1] = make_float4(Rp[4] - Rg[4], Rp[5] - Rg[5], Rp[6] - Rg[6], Rp[7] - Rg[7]);
    dst[2] = make_float4(Rp[8] - Rg[8], 0.0f, 0.0f, 0.0f);
}

// Kernel 2: persistent streaming (R8 structure). 4 points/thread/row in registers,
// vector D loads, approx sqrt. One reduce + one atomic per CTA.
__global__ __launch_bounds__(THREADS, 6)
void add_loss_kernel(const float* __restrict__ point, float* __restrict__ out) {
    __shared__ float warp_sums[THREADS / 32];

    const int t = threadIdx.x;
    float acc = 0.0f;

    // Incremental pointers (cuts per-iteration 64-bit IMADs).
    const float4* __restrict__ p = (const float4*)(point) + (size_t)blockIdx.x * (N_PTS * 3 / 4) + 3 * t;
    const float4* __restrict__ d = (const float4*)(g_D) + (size_t)blockIdx.x * 3;
    const size_t p_step = (size_t)GRID * (N_PTS * 3 / 4);
    const size_t d_step = (size_t)GRID * 3;

    #pragma unroll 1
    for (int b = blockIdx.x; b < B_DIM; b += GRID, p += p_step, d += d_step) {
        // Batch loads: 3 point LDG.128 + 3 D LDG.128 (broadcast, L1-hot).
        const float4 av = p[0];
        const float4 bv = p[1];
        const float4 cv = p[2];
        const float4 D0 = d[0];
        const float4 D1 = d[1];
        const float4 D2 = d[2];

        const float d00 = D0.x, d01 = D0.y, d02 = D0.z;
        const float d10 = D0.w, d11 = D1.x, d12 = D1.y;
        const float d20 = D1.z, d21 = D1.w, d22 = D2.x;

        const float px[4] = {av.x, av.w, bv.z, cv.y};
        const float py[4] = {av.y, bv.x, bv.w, cv.z};
        const float pz[4] = {av.z, bv.y, cv.x, cv.w};
        #pragma unroll
        for (int i = 0; i < 4; i++) {
            const float q0 = fmaf(px[i], d00, fmaf(py[i], d10, pz[i] * d20));
            const float q1 = fmaf(px[i], d01, fmaf(py[i], d11, pz[i] * d21));
            const float q2 = fmaf(px[i], d02, fmaf(py[i], d12, pz[i] * d22));
            acc += fast_sqrt(fmaf(q0, q0, fmaf(q1, q1, q2 * q2)));
        }
    }

    // One reduce + one atomic per CTA.
    #pragma unroll
    for (int off = 16; off > 0; off >>= 1)
        acc += __shfl_xor_sync(0xffffffffu, acc, off);
    if ((t & 31) == 0) warp_sums[t >> 5] = acc;
    __syncthreads();

    if (t == 0) {
        float s = 0.0f;
        #pragma unroll
        for (int w = 0; w < THREADS / 32; w++) s += warp_sums[w];
        atomicAdd(&g_acc, (double)s);
        __threadfence();
        const unsigned int ticket = atomicAdd(&g_ticket, 1u);
        if (ticket == (unsigned int)(gridDim.x - 1)) {
            __threadfence();
            const double total = atomicAdd(&g_acc, 0.0);
            out[0] = (float)(total * (1.0 / ((double)B_DIM * (double)N_PTS)));
        }
    }
}

extern "C" void kernel_launch(void* const* d_in, const int* in_sizes, int n_in,
                              void* d_out, int out_size) {
    const float* pred  = (const float*)d_in[0];   // (8192, 4)
    const float* mode  = (const float*)d_in[1];   // (8192,)
    const float* gt    = (const float*)d_in[2];   // (8192, 3)
    const float* point = (const float*)d_in[3];   // (8192, 1024, 3)
    float* out = (float*)d_out;

    precompute_kernel<<<B_DIM / 256, 256>>>(pred, mode, gt);
    add_loss_kernel<<<GRID, THREADS>>>(point, out);
}